// round 16
// baseline (speedup 1.0000x reference)
#include <cuda_runtime.h>
#include <cuda_bf16.h>

#define DIM     65536
#define BATCH   32
#define TILE    8192       // 2^13 amps per tile
#define THREADS 512

// Scratch (float2 = interleaved re,im). Static: no runtime alloc.
__device__ float2 d_s1[BATCH * DIM];
__device__ float2 d_s2[BATCH * DIM];

// GF(2) swizzle for float2 (8B) smem tiles: fold tile bits 4..8 into the
// bank-pair bits 0..3 with masks {1,2,4,8,3}. For every window used below the
// half-warp lane-position set maps to rank-4 mod 16 -> conflict-free LDS.64.
__device__ __forceinline__ int SWZ2(int i) {
    int x = (((i >> 4) & 1) * 1) ^ (((i >> 5) & 1) * 2)
          ^ (((i >> 6) & 1) * 4) ^ (((i >> 7) & 1) * 8)
          ^ (((i >> 8) & 1) * 3);
    return i ^ x;
}

// ---------------------------------------------------------------------------
// Address maps (identical to the 43.5us kernel).
//  pass1 tile: l0=g0, l1..l12=g4..g15;  hv = g1,g2,g3
//  pass2 tile: m0..4=g0..4, m5..12=g8..15; hv = g5,g6,g7
//  pass3 tile: n0..9=g0..9, n10..12=g13..15; hv = g10,g11,g12
//  d_s1 bits: 0..8=g7..g15, 9=g0, 10..12=g1..3, 13..15=g4..6
//  d_s2 bits: natural g0..g15
// ---------------------------------------------------------------------------
struct MapIn {        // pass1 W1 <- input
    int base, hv;
    __device__ __forceinline__ int operator()(int a) const {
        return base + ((a & 1) | (hv << 1) | ((a >> 1) << 4));
    }
};
struct MapS1Store {   // pass1 W4 -> d_s1
    int base, hv;
    __device__ __forceinline__ int operator()(int a) const {
        return base + ((a >> 4) | ((a & 1) << 9) | (hv << 10) | (((a >> 1) & 7) << 13));
    }
};
struct MapS1Load {    // pass2 WA <- d_s1
    int base, hv;
    __device__ __forceinline__ int operator()(int a) const {
        return base + (((hv >> 2) & 1) | (((a >> 5) & 0xFF) << 1) | ((a & 1) << 9)
                     | (((a >> 1) & 7) << 10) | (((a >> 4) & 1) << 13) | ((hv & 3) << 14));
    }
};
struct MapS2Store {   // pass2 WD -> d_s2
    int base, hv;
    __device__ __forceinline__ int operator()(int a) const {
        return base + ((a & 31) | (hv << 5) | ((a >> 5) << 8));
    }
};
struct MapS2Load {    // pass3 WX <- d_s2
    int base, hv;
    __device__ __forceinline__ int operator()(int a) const {
        return base + ((a & 0x3FF) | (hv << 10) | ((a >> 10) << 13));
    }
};

// ---------------------------------------------------------------------------
// Per-CTA fused unitaries U = RZ*RY*RX into smem: sU[(l*16+q)*8 + k]
// qubit q <-> global bit g(15-q); gate on g_k uses U[layer][15-k].
// ---------------------------------------------------------------------------
__device__ __forceinline__ void compute_U(const float* __restrict__ thetas, float* sU) {
    int t = threadIdx.x;
    if (t < 32) {
        int l = t >> 4, q = t & 15;
        float th0 = thetas[l * 48 + 0 * 16 + q];
        float th1 = thetas[l * 48 + 1 * 16 + q];
        float th2 = thetas[l * 48 + 2 * 16 + q];
        float c0, s0, c1, s1, cz, sz;
        sincosf(0.5f * th0, &s0, &c0);
        sincosf(0.5f * th1, &s1, &c1);
        sincosf(0.5f * th2, &sz, &cz);
        float m00r =  c1 * c0, m00i =  s1 * s0;
        float m01r = -s1 * c0, m01i = -c1 * s0;
        float m10r =  s1 * c0, m10i = -c1 * s0;
        float m11r =  c1 * c0, m11i = -s1 * s0;
        float* u = sU + (l * 16 + q) * 8;
        u[0] = m00r * cz + m00i * sz;  u[1] = m00i * cz - m00r * sz;
        u[2] = m01r * cz + m01i * sz;  u[3] = m01i * cz - m01r * sz;
        u[4] = m10r * cz - m10i * sz;  u[5] = m10i * cz + m10r * sz;
        u[6] = m11r * cz - m11i * sz;  u[7] = m11i * cz + m11r * sz;
    }
    __syncthreads();
}

// ---------------------------------------------------------------------------
// 4-bit register window over 13-bit tile index; smem tile is float2[TILE].
// ---------------------------------------------------------------------------
template <int WMASK>
__device__ __forceinline__ int expand_t(int t) {
    int base = 0, tb = 0;
    #pragma unroll
    for (int b = 0; b < 13; b++) {
        if (!(WMASK & (1 << b))) { base |= ((t >> tb) & 1) << b; tb++; }
    }
    return base;
}

template <int W0, int W1, int W2, int W3>
struct Sweep4 {
    static constexpr int WMASK = (1<<W0)|(1<<W1)|(1<<W2)|(1<<W3);
    int sraw;
    float ar[16], ai[16];

    static __device__ __forceinline__ constexpr int place(int r) {
        return (((r>>0)&1)<<W0)|(((r>>1)&1)<<W1)|(((r>>2)&1)<<W2)|(((r>>3)&1)<<W3);
    }
    __device__ __forceinline__ void init() { sraw = expand_t<WMASK>((int)threadIdx.x); }

    __device__ __forceinline__ void ld(const float2* sm2) {
        init();
        #pragma unroll
        for (int r = 0; r < 16; r++) {
            float2 v = sm2[SWZ2(sraw | place(r))];
            ar[r] = v.x; ai[r] = v.y;
        }
    }
    __device__ __forceinline__ void st(float2* sm2) {
        #pragma unroll
        for (int r = 0; r < 16; r++) {
            float2 v; v.x = ar[r]; v.y = ai[r];
            sm2[SWZ2(sraw | place(r))] = v;
        }
        __syncthreads();
    }
    template <class F>
    __device__ __forceinline__ void ld_in(const float* gre, const float* gim, F f) {
        init();
        #pragma unroll
        for (int r = 0; r < 16; r++) {
            int gi = f(sraw | place(r));
            ar[r] = gre[gi]; ai[r] = gim[gi];
        }
    }
    template <class F>
    __device__ __forceinline__ void ld_f2(const float2* g, F f) {
        init();
        #pragma unroll
        for (int r = 0; r < 16; r++) {
            float2 v = g[f(sraw | place(r))];
            ar[r] = v.x; ai[r] = v.y;
        }
    }
    template <class F>
    __device__ __forceinline__ void st_f2(float2* g, F f) {
        #pragma unroll
        for (int r = 0; r < 16; r++) {
            float2 v; v.x = ar[r]; v.y = ai[r];
            g[f(sraw | place(r))] = v;
        }
    }
    template <int KB>
    __device__ __forceinline__ void g1q(const float* __restrict__ u) {
        float u0=u[0],u1=u[1],u2=u[2],u3=u[3],u4=u[4],u5=u[5],u6=u[6],u7=u[7];
        #pragma unroll
        for (int p = 0; p < 8; p++) {
            int lo = p & ((1 << KB) - 1);
            int i0 = ((p >> KB) << (KB + 1)) | lo;
            int i1 = i0 | (1 << KB);
            float xr = ar[i0], xi = ai[i0], yr = ar[i1], yi = ai[i1];
            ar[i0] = u0*xr - u1*xi + u2*yr - u3*yi;
            ai[i0] = u0*xi + u1*xr + u2*yi + u3*yr;
            ar[i1] = u4*xr - u5*xi + u6*yr - u7*yi;
            ai[i1] = u4*xi + u5*xr + u6*yi + u7*yr;
        }
    }
    template <int CB, int TB>
    __device__ __forceinline__ void cx() {
        #pragma unroll
        for (int p = 0; p < 16; p++) {
            if (((p >> CB) & 1) && !((p >> TB) & 1)) {
                int q = p | (1 << TB);
                float tr = ar[p]; ar[p] = ar[q]; ar[q] = tr;
                float ti = ai[p]; ai[p] = ai[q]; ai[q] = ti;
            }
        }
    }
};

#define SMEM_FLOATS (2 * TILE + 2 * 16 * 8)

// ---------------------------------------------------------------------------
// Pass 1: set {g0, g4..g15} (l0=g0, l1..12=g4..15); hv = g1..3.
// L1 1q g0, g4..g15 (13); L1 chain C(15,14)..C(5,4) (11).
// ---------------------------------------------------------------------------
__global__ void __launch_bounds__(THREADS, 2)
pass1_kernel(const float* __restrict__ thetas,
             const float* __restrict__ in_re, const float* __restrict__ in_im) {
    extern __shared__ float sm[];
    float2* sm2 = (float2*)sm; float* sU = sm + 2 * TILE;
    int b = blockIdx.x >> 3, hv = blockIdx.x & 7;

    { Sweep4<9,10,11,12> s;                       // g12..15
      MapIn f; f.base = b * DIM; f.hv = hv;
      s.ld_in(in_re, in_im, f);                   // prefetch (no sU dependence)
      compute_U(thetas, sU);                      // overlaps load latency; barrier
      s.g1q<0>(sU+3*8); s.g1q<1>(sU+2*8); s.g1q<2>(sU+1*8); s.g1q<3>(sU+0*8);
      s.cx<3,2>(); s.cx<2,1>(); s.cx<1,0>();      // C(15,14),(14,13),(13,12)
      s.st(sm2); }
    { Sweep4<6,7,8,9> s; s.ld(sm2);               // g9..12
      s.g1q<0>(sU+6*8); s.g1q<1>(sU+5*8); s.g1q<2>(sU+4*8);
      s.cx<3,2>(); s.cx<2,1>(); s.cx<1,0>();      // C(12,11),(11,10),(10,9)
      s.st(sm2); }
    { Sweep4<3,4,5,6> s; s.ld(sm2);               // g6..9
      s.g1q<0>(sU+9*8); s.g1q<1>(sU+8*8); s.g1q<2>(sU+7*8);
      s.cx<3,2>(); s.cx<2,1>(); s.cx<1,0>();      // C(9,8),(8,7),(7,6)
      s.st(sm2); }
    { Sweep4<0,1,2,3> s; s.ld(sm2);               // g0,g4,g5,g6
      s.g1q<0>(sU+15*8);                          // L1 1q g0
      s.g1q<1>(sU+11*8); s.g1q<2>(sU+10*8);       // L1 1q g4,g5
      s.cx<3,2>(); s.cx<2,1>();                   // C(6,5),(5,4)
      MapS1Store f; f.base = b * DIM; f.hv = hv;
      s.st_f2(d_s1, f); }

    cudaTriggerProgrammaticLaunchCompletion();
}

// ---------------------------------------------------------------------------
// Pass 2: set {g0..4, g8..15} (m0..4=g0..4, m5..12=g8..15); hv = g5..7.
// L1 1q g1,g2,g3 + chain C(4,3),(3,2),(2,1),(1,0),(0,15);
// L2 1q g0,g1,g8..g15 (10); L2 chain C(15,14)..C(9,8) (7).
// ---------------------------------------------------------------------------
__global__ void __launch_bounds__(THREADS, 2)
pass2_kernel(const float* __restrict__ thetas) {
    extern __shared__ float sm[];
    float2* sm2 = (float2*)sm; float* sU = sm + 2 * TILE;
    int b = blockIdx.x >> 3, hv = blockIdx.x & 7;
    const float* U1 = sU + 16 * 8;

    compute_U(thetas, sU);          // independent of pass1 output
    cudaGridDependencySynchronize();

    { Sweep4<1,2,3,4> s;                          // g1..4
      MapS1Load f; f.base = b * DIM; f.hv = hv;
      s.ld_f2(d_s1, f);
      s.g1q<0>(sU+14*8); s.g1q<1>(sU+13*8); s.g1q<2>(sU+12*8); // L1 1q g1,g2,g3
      s.cx<3,2>(); s.cx<2,1>(); s.cx<1,0>();      // L1 C(4,3),(3,2),(2,1)
      s.st(sm2); }
    { Sweep4<0,1,11,12> s; s.ld(sm2);             // g0,g1,g14,g15
      s.cx<1,0>(); s.cx<0,3>();                   // L1 C(1,0), C(0,15)
      s.g1q<0>(U1+15*8); s.g1q<1>(U1+14*8);       // L2 1q g0,g1
      s.g1q<2>(U1+1*8);  s.g1q<3>(U1+0*8);        // L2 1q g14,g15
      s.cx<3,2>();                                // L2 C(15,14)
      s.st(sm2); }
    { Sweep4<8,9,10,11> s; s.ld(sm2);             // g11..14
      s.g1q<0>(U1+4*8); s.g1q<1>(U1+3*8); s.g1q<2>(U1+2*8);    // L2 1q g11,g12,g13
      s.cx<3,2>(); s.cx<2,1>(); s.cx<1,0>();      // L2 C(14,13),(13,12),(12,11)
      s.st(sm2); }
    { Sweep4<5,6,7,8> s; s.ld(sm2);               // g8..11
      s.g1q<0>(U1+7*8); s.g1q<1>(U1+6*8); s.g1q<2>(U1+5*8);    // L2 1q g8,g9,g10
      s.cx<3,2>(); s.cx<2,1>(); s.cx<1,0>();      // L2 C(11,10),(10,9),(9,8)
      MapS2Store f; f.base = b * DIM; f.hv = hv;
      s.st_f2(d_s2, f); }

    cudaTriggerProgrammaticLaunchCompletion();
}

// ---------------------------------------------------------------------------
// Pass 3: set {g0..9, g13..15} (n0..9=g0..9, n10..12=g13..15); hv = g10..12.
// L2 1q g2..g7 (6); L2 chain C(8,7)..C(1,0),C(0,15). |psi|^2 out.
// ---------------------------------------------------------------------------
__global__ void __launch_bounds__(THREADS, 2)
pass3_kernel(const float* __restrict__ thetas, float* __restrict__ probs) {
    extern __shared__ float sm[];
    float2* sm2 = (float2*)sm; float* sU = sm + 2 * TILE;
    int b = blockIdx.x >> 3, hv = blockIdx.x & 7;
    const float* U1 = sU + 16 * 8;

    compute_U(thetas, sU);
    cudaGridDependencySynchronize();

    { Sweep4<5,6,7,8> s;                          // g5..8
      MapS2Load f; f.base = b * DIM; f.hv = hv;
      s.ld_f2(d_s2, f);
      s.g1q<0>(U1+10*8); s.g1q<1>(U1+9*8); s.g1q<2>(U1+8*8);   // L2 1q g5,g6,g7
      s.cx<3,2>(); s.cx<2,1>(); s.cx<1,0>();      // L2 C(8,7),(7,6),(6,5)
      s.st(sm2); }
    { Sweep4<2,3,4,5> s; s.ld(sm2);               // g2..5
      s.g1q<0>(U1+13*8); s.g1q<1>(U1+12*8); s.g1q<2>(U1+11*8); // L2 1q g2,g3,g4
      s.cx<3,2>(); s.cx<2,1>(); s.cx<1,0>();      // L2 C(5,4),(4,3),(3,2)
      s.st(sm2); }
    { Sweep4<0,1,2,12> s; s.ld(sm2);              // g0,g1,g2,g15
      s.cx<2,1>(); s.cx<1,0>(); s.cx<0,3>();      // L2 C(2,1),(1,0),(0,15)
      // probs: regs 0..7 = g0..2 (g15=0), regs 8..15 = +32768
      int out = (((s.sraw >> 3) & 0x7F) << 3) | (hv << 10) | (((s.sraw >> 10) & 3) << 13);
      float4* p4 = (float4*)(probs + b * DIM + out);
      float4 w;
      w.x = s.ar[0]*s.ar[0] + s.ai[0]*s.ai[0];
      w.y = s.ar[1]*s.ar[1] + s.ai[1]*s.ai[1];
      w.z = s.ar[2]*s.ar[2] + s.ai[2]*s.ai[2];
      w.w = s.ar[3]*s.ar[3] + s.ai[3]*s.ai[3];
      p4[0] = w;
      w.x = s.ar[4]*s.ar[4] + s.ai[4]*s.ai[4];
      w.y = s.ar[5]*s.ar[5] + s.ai[5]*s.ai[5];
      w.z = s.ar[6]*s.ar[6] + s.ai[6]*s.ai[6];
      w.w = s.ar[7]*s.ar[7] + s.ai[7]*s.ai[7];
      p4[1] = w;
      float4* p4h = (float4*)(probs + b * DIM + out + 32768);
      w.x = s.ar[8]*s.ar[8] + s.ai[8]*s.ai[8];
      w.y = s.ar[9]*s.ar[9] + s.ai[9]*s.ai[9];
      w.z = s.ar[10]*s.ar[10] + s.ai[10]*s.ai[10];
      w.w = s.ar[11]*s.ar[11] + s.ai[11]*s.ai[11];
      p4h[0] = w;
      w.x = s.ar[12]*s.ar[12] + s.ai[12]*s.ai[12];
      w.y = s.ar[13]*s.ar[13] + s.ai[13]*s.ai[13];
      w.z = s.ar[14]*s.ar[14] + s.ai[14]*s.ai[14];
      w.w = s.ar[15]*s.ar[15] + s.ai[15]*s.ai[15];
      p4h[1] = w; }
}

extern "C" void kernel_launch(void* const* d_in, const int* in_sizes, int n_in,
                              void* d_out, int out_size) {
    const float* thetas = (const float*)d_in[0];
    const float* st_re  = (const float*)d_in[1];
    const float* st_im  = (const float*)d_in[2];
    float* probs = (float*)d_out;

    const int SMEM = SMEM_FLOATS * sizeof(float);  // 64 KB + 1 KB
    cudaFuncSetAttribute(pass1_kernel, cudaFuncAttributeMaxDynamicSharedMemorySize, SMEM);
    cudaFuncSetAttribute(pass2_kernel, cudaFuncAttributeMaxDynamicSharedMemorySize, SMEM);
    cudaFuncSetAttribute(pass3_kernel, cudaFuncAttributeMaxDynamicSharedMemorySize, SMEM);

    dim3 grid(BATCH * 8);   // 256 CTAs, 2 per SM resident

    pass1_kernel<<<grid, THREADS, SMEM>>>(thetas, st_re, st_im);

    cudaLaunchAttribute attrs[1];
    attrs[0].id = cudaLaunchAttributeProgrammaticStreamSerialization;
    attrs[0].val.programmaticStreamSerializationAllowed = 1;

    cudaLaunchConfig_t cfg = {};
    cfg.gridDim = grid;
    cfg.blockDim = dim3(THREADS);
    cfg.dynamicSmemBytes = SMEM;
    cfg.stream = 0;
    cfg.attrs = attrs;
    cfg.numAttrs = 1;

    cudaLaunchKernelEx(&cfg, pass2_kernel, thetas);
    cudaLaunchKernelEx(&cfg, pass3_kernel, thetas, probs);
}

// round 17
// speedup vs baseline: 1.0491x; 1.0491x over previous
#include <cuda_runtime.h>
#include <cuda_bf16.h>

#define DIM     65536
#define BATCH   32
#define TILE    8192       // 2^13 amps per tile
#define THREADS 256        // 32 amps per thread (5-bit windows)

// Scratch (float2 = interleaved re,im). Static: no runtime alloc.
__device__ float2 d_s1[BATCH * DIM];
__device__ float2 d_s2[BATCH * DIM];

// GF(2) swizzle for float2 (8B) smem tiles: fold tile bits 4..8 into the
// bank-pair bits 0..3 with masks {1,2,4,8,3}. Verified rank-4 (mod 16) for
// every window's half-warp lane-position set used below.
__device__ __forceinline__ int SWZ2(int i) {
    int x = (((i >> 4) & 1) * 1) ^ (((i >> 5) & 1) * 2)
          ^ (((i >> 6) & 1) * 4) ^ (((i >> 7) & 1) * 8)
          ^ (((i >> 8) & 1) * 3);
    return i ^ x;
}

// ---------------------------------------------------------------------------
// Tilings (qubit q <-> global bit g(15-q); gate on g_k uses U[layer][15-k]):
//  pass1 tile: l0=g0, l1..l12=g4..g15;  hv = g1,g2,g3
//  pass2 tile: m0..4=g0..4, m5..12=g8..15; hv = g5,g6,g7
//  pass3 tile: n0..9=g0..9, n10..12=g13..15; hv = g10,g11,g12
// Scratch layouts (state bit -> float2-index bit):
//  d_s1: g8..g12->0..4, g13..g15->5..7, g0->8, g4..g7->9..12, g1..g3->13..15
//        (both boundary sweeps have lanes on g8..g12 -> 256B-perfect both sides)
//  d_s2: natural g0..g15
// (bijectivity + producer/consumer consistency verified bit-by-bit)
// ---------------------------------------------------------------------------
struct MapIn {        // pass1 WA <- input
    int base, hv;
    __device__ __forceinline__ int operator()(int a) const {
        return base + ((a & 1) | (hv << 1) | ((a >> 1) << 4));
    }
};
struct MapS1Store {   // pass1 WC -> d_s1
    int base, hv;
    __device__ __forceinline__ int operator()(int a) const {
        return base + (((a >> 5) & 31) | (((a >> 10) & 7) << 5) | ((a & 1) << 8)
                     | (((a >> 1) & 15) << 9) | (hv << 13));
    }
};
struct MapS1Load {    // pass2 W1 <- d_s1
    int base, hv;
    __device__ __forceinline__ int operator()(int m) const {
        return base + (((m >> 5) & 31) | (((m >> 10) & 7) << 5) | ((m & 1) << 8)
                     | (((m >> 4) & 1) << 9) | (hv << 10) | (((m >> 1) & 7) << 13));
    }
};
struct MapS2Store {   // pass2 W3 -> d_s2
    int base, hv;
    __device__ __forceinline__ int operator()(int m) const {
        return base + ((m & 31) | (hv << 5) | (((m >> 5) & 0xFF) << 8));
    }
};
struct MapS2Load {    // pass3 V1 <- d_s2
    int base, hv;
    __device__ __forceinline__ int operator()(int n) const {
        return base + ((n & 0x3FF) | (hv << 10) | (((n >> 10) & 7) << 13));
    }
};

// ---------------------------------------------------------------------------
// Per-CTA fused unitaries U = RZ*RY*RX into smem: sU[(l*16+q)*8 + k]
// ---------------------------------------------------------------------------
__device__ __forceinline__ void compute_U(const float* __restrict__ thetas, float* sU) {
    int t = threadIdx.x;
    if (t < 32) {
        int l = t >> 4, q = t & 15;
        float th0 = thetas[l * 48 + 0 * 16 + q];
        float th1 = thetas[l * 48 + 1 * 16 + q];
        float th2 = thetas[l * 48 + 2 * 16 + q];
        float c0, s0, c1, s1, cz, sz;
        sincosf(0.5f * th0, &s0, &c0);
        sincosf(0.5f * th1, &s1, &c1);
        sincosf(0.5f * th2, &sz, &cz);
        float m00r =  c1 * c0, m00i =  s1 * s0;
        float m01r = -s1 * c0, m01i = -c1 * s0;
        float m10r =  s1 * c0, m10i = -c1 * s0;
        float m11r =  c1 * c0, m11i = -s1 * s0;
        float* u = sU + (l * 16 + q) * 8;
        u[0] = m00r * cz + m00i * sz;  u[1] = m00i * cz - m00r * sz;
        u[2] = m01r * cz + m01i * sz;  u[3] = m01i * cz - m01r * sz;
        u[4] = m10r * cz - m10i * sz;  u[5] = m10i * cz + m10r * sz;
        u[6] = m11r * cz - m11i * sz;  u[7] = m11i * cz + m11r * sz;
    }
    __syncthreads();
}

// ---------------------------------------------------------------------------
// 5-bit register window over 13-bit tile index: 32 amps per thread.
// ---------------------------------------------------------------------------
template <int WMASK>
__device__ __forceinline__ int expand_t(int t) {
    int base = 0, tb = 0;
    #pragma unroll
    for (int b = 0; b < 13; b++) {
        if (!(WMASK & (1 << b))) { base |= ((t >> tb) & 1) << b; tb++; }
    }
    return base;
}

template <int W0, int W1, int W2, int W3, int W4>
struct Sweep5 {
    static constexpr int WMASK = (1<<W0)|(1<<W1)|(1<<W2)|(1<<W3)|(1<<W4);
    int sraw;
    float ar[32], ai[32];

    static __device__ __forceinline__ constexpr int place(int r) {
        return (((r>>0)&1)<<W0)|(((r>>1)&1)<<W1)|(((r>>2)&1)<<W2)
             | (((r>>3)&1)<<W3)|(((r>>4)&1)<<W4);
    }
    __device__ __forceinline__ void init() { sraw = expand_t<WMASK>((int)threadIdx.x); }

    __device__ __forceinline__ void ld(const float2* sm2) {
        init();
        #pragma unroll
        for (int r = 0; r < 32; r++) {
            float2 v = sm2[SWZ2(sraw | place(r))];
            ar[r] = v.x; ai[r] = v.y;
        }
    }
    __device__ __forceinline__ void st(float2* sm2) {
        #pragma unroll
        for (int r = 0; r < 32; r++) {
            float2 v; v.x = ar[r]; v.y = ai[r];
            sm2[SWZ2(sraw | place(r))] = v;
        }
        __syncthreads();
    }
    template <class F>
    __device__ __forceinline__ void ld_in(const float* gre, const float* gim, F f) {
        init();
        #pragma unroll
        for (int r = 0; r < 32; r++) {
            int gi = f(sraw | place(r));
            ar[r] = gre[gi]; ai[r] = gim[gi];
        }
    }
    template <class F>
    __device__ __forceinline__ void ld_f2(const float2* g, F f) {
        init();
        #pragma unroll
        for (int r = 0; r < 32; r++) {
            float2 v = g[f(sraw | place(r))];
            ar[r] = v.x; ai[r] = v.y;
        }
    }
    template <class F>
    __device__ __forceinline__ void st_f2(float2* g, F f) {
        #pragma unroll
        for (int r = 0; r < 32; r++) {
            float2 v; v.x = ar[r]; v.y = ai[r];
            g[f(sraw | place(r))] = v;
        }
    }
    template <int KB>
    __device__ __forceinline__ void g1q(const float* __restrict__ u) {
        float u0=u[0],u1=u[1],u2=u[2],u3=u[3],u4=u[4],u5=u[5],u6=u[6],u7=u[7];
        #pragma unroll
        for (int p = 0; p < 16; p++) {
            int lo = p & ((1 << KB) - 1);
            int i0 = ((p >> KB) << (KB + 1)) | lo;
            int i1 = i0 | (1 << KB);
            float xr = ar[i0], xi = ai[i0], yr = ar[i1], yi = ai[i1];
            ar[i0] = u0*xr - u1*xi + u2*yr - u3*yi;
            ai[i0] = u0*xi + u1*xr + u2*yi + u3*yr;
            ar[i1] = u4*xr - u5*xi + u6*yr - u7*yi;
            ai[i1] = u4*xi + u5*xr + u6*yi + u7*yr;
        }
    }
    template <int CB, int TB>
    __device__ __forceinline__ void cx() {
        #pragma unroll
        for (int p = 0; p < 32; p++) {
            if (((p >> CB) & 1) && !((p >> TB) & 1)) {
                int q = p | (1 << TB);
                float tr = ar[p]; ar[p] = ar[q]; ar[q] = tr;
                float ti = ai[p]; ai[p] = ai[q]; ai[q] = ti;
            }
        }
    }
};

#define SMEM_FLOATS (2 * TILE + 2 * 16 * 8)

// ---------------------------------------------------------------------------
// Pass 1: L1 1q g0, g4..g15 (13); L1 chain C(15,14)..C(5,4).  3 windows.
// ---------------------------------------------------------------------------
__global__ void __launch_bounds__(THREADS, 2)
pass1_kernel(const float* __restrict__ thetas,
             const float* __restrict__ in_re, const float* __restrict__ in_im) {
    extern __shared__ float sm[];
    float2* sm2 = (float2*)sm; float* sU = sm + 2 * TILE;
    int b = blockIdx.x >> 3, hv = blockIdx.x & 7;

    { Sweep5<8,9,10,11,12> s;                     // g11..g15
      MapIn f; f.base = b * DIM; f.hv = hv;
      s.ld_in(in_re, in_im, f);                   // prefetch (no sU dependence)
      compute_U(thetas, sU);                      // overlaps load latency; barrier
      s.g1q<0>(sU+4*8); s.g1q<1>(sU+3*8); s.g1q<2>(sU+2*8);
      s.g1q<3>(sU+1*8); s.g1q<4>(sU+0*8);         // 1q g11..g15
      s.cx<4,3>(); s.cx<3,2>(); s.cx<2,1>(); s.cx<1,0>(); // C(15,14)..C(12,11)
      s.st(sm2); }
    { Sweep5<4,5,6,7,8> s; s.ld(sm2);             // g7..g11
      s.g1q<0>(sU+8*8); s.g1q<1>(sU+7*8); s.g1q<2>(sU+6*8); s.g1q<3>(sU+5*8); // 1q g7..g10
      s.cx<4,3>(); s.cx<3,2>(); s.cx<2,1>(); s.cx<1,0>(); // C(11,10)..C(8,7)
      s.st(sm2); }
    { Sweep5<0,1,2,3,4> s; s.ld(sm2);             // g0,g4,g5,g6,g7
      s.g1q<0>(sU+15*8);                          // 1q g0
      s.g1q<1>(sU+11*8); s.g1q<2>(sU+10*8); s.g1q<3>(sU+9*8); // 1q g4,g5,g6
      s.cx<4,3>(); s.cx<3,2>(); s.cx<2,1>();      // C(7,6),(6,5),(5,4)
      MapS1Store f; f.base = b * DIM; f.hv = hv;
      s.st_f2(d_s1, f); }

    cudaTriggerProgrammaticLaunchCompletion();
}

// ---------------------------------------------------------------------------
// Pass 2: L1 1q g1,g2,g3 + chain C(4,3)..C(1,0),C(0,15);
//         L2 1q g8..g15; L2 chain C(15,14)..C(9,8).  3 windows.
// ---------------------------------------------------------------------------
__global__ void __launch_bounds__(THREADS, 2)
pass2_kernel(const float* __restrict__ thetas) {
    extern __shared__ float sm[];
    float2* sm2 = (float2*)sm; float* sU = sm + 2 * TILE;
    int b = blockIdx.x >> 3, hv = blockIdx.x & 7;
    const float* U1 = sU + 16 * 8;

    compute_U(thetas, sU);          // independent of pass1 output
    cudaGridDependencySynchronize();

    { Sweep5<0,1,2,3,4> s;                        // g0..g4
      MapS1Load f; f.base = b * DIM; f.hv = hv;
      s.ld_f2(d_s1, f);
      s.g1q<1>(sU+14*8); s.g1q<2>(sU+13*8); s.g1q<3>(sU+12*8); // L1 1q g1,g2,g3
      s.cx<4,3>(); s.cx<3,2>(); s.cx<2,1>(); s.cx<1,0>(); // L1 C(4,3)..C(1,0)
      s.st(sm2); }
    { Sweep5<0,9,10,11,12> s; s.ld(sm2);          // g0,g12,g13,g14,g15
      s.cx<0,4>();                                // L1 C(0,15)
      s.g1q<4>(U1+0*8); s.g1q<3>(U1+1*8); s.g1q<2>(U1+2*8); s.g1q<1>(U1+3*8); // L2 1q g15,g14,g13,g12
      s.cx<4,3>(); s.cx<3,2>(); s.cx<2,1>();      // L2 C(15,14),(14,13),(13,12)
      s.st(sm2); }
    { Sweep5<5,6,7,8,9> s; s.ld(sm2);             // g8..g12
      s.g1q<0>(U1+7*8); s.g1q<1>(U1+6*8); s.g1q<2>(U1+5*8); s.g1q<3>(U1+4*8); // L2 1q g8..g11
      s.cx<4,3>(); s.cx<3,2>(); s.cx<2,1>(); s.cx<1,0>(); // L2 C(12,11)..C(9,8)
      MapS2Store f; f.base = b * DIM; f.hv = hv;
      s.st_f2(d_s2, f); }

    cudaTriggerProgrammaticLaunchCompletion();
}

// ---------------------------------------------------------------------------
// Pass 3: L2 1q g0..g7; L2 chain C(8,7)..C(1,0),C(0,15). |psi|^2 out. 3 windows.
// ---------------------------------------------------------------------------
__global__ void __launch_bounds__(THREADS, 2)
pass3_kernel(const float* __restrict__ thetas, float* __restrict__ probs) {
    extern __shared__ float sm[];
    float2* sm2 = (float2*)sm; float* sU = sm + 2 * TILE;
    int b = blockIdx.x >> 3, hv = blockIdx.x & 7;
    const float* U1 = sU + 16 * 8;

    compute_U(thetas, sU);
    cudaGridDependencySynchronize();

    { Sweep5<4,5,6,7,8> s;                        // g4..g8
      MapS2Load f; f.base = b * DIM; f.hv = hv;
      s.ld_f2(d_s2, f);
      s.g1q<0>(U1+11*8); s.g1q<1>(U1+10*8); s.g1q<2>(U1+9*8); s.g1q<3>(U1+8*8); // L2 1q g4..g7
      s.cx<4,3>(); s.cx<3,2>(); s.cx<2,1>(); s.cx<1,0>(); // L2 C(8,7)..C(5,4)
      s.st(sm2); }
    { Sweep5<0,1,2,3,4> s; s.ld(sm2);             // g0..g4
      s.g1q<0>(U1+15*8); s.g1q<1>(U1+14*8); s.g1q<2>(U1+13*8); s.g1q<3>(U1+12*8); // L2 1q g0..g3
      s.cx<4,3>(); s.cx<3,2>(); s.cx<2,1>(); s.cx<1,0>(); // L2 C(4,3)..C(1,0)
      s.st(sm2); }
    { Sweep5<0,1,2,3,12> s; s.ld(sm2);            // g0,g1,g2,g3,g15
      s.cx<0,4>();                                // L2 C(0,15)
      // probs: regs 0..15 -> g0..g3 contiguous (g15=0), regs 16..31 -> +32768
      int out = (((s.sraw >> 4) & 0x3F) << 4) | (hv << 10) | (((s.sraw >> 10) & 3) << 13);
      float* pb = probs + b * DIM + out;
      #pragma unroll
      for (int h = 0; h < 2; h++) {
          float* dst = pb + h * 32768;
          #pragma unroll
          for (int q = 0; q < 4; q++) {
              int r = h * 16 + q * 4;
              float4 w;
              w.x = s.ar[r+0]*s.ar[r+0] + s.ai[r+0]*s.ai[r+0];
              w.y = s.ar[r+1]*s.ar[r+1] + s.ai[r+1]*s.ai[r+1];
              w.z = s.ar[r+2]*s.ar[r+2] + s.ai[r+2]*s.ai[r+2];
              w.w = s.ar[r+3]*s.ar[r+3] + s.ai[r+3]*s.ai[r+3];
              ((float4*)dst)[q] = w;
          }
      } }
}

extern "C" void kernel_launch(void* const* d_in, const int* in_sizes, int n_in,
                              void* d_out, int out_size) {
    const float* thetas = (const float*)d_in[0];
    const float* st_re  = (const float*)d_in[1];
    const float* st_im  = (const float*)d_in[2];
    float* probs = (float*)d_out;

    const int SMEM = SMEM_FLOATS * sizeof(float);  // 64 KB + 1 KB
    cudaFuncSetAttribute(pass1_kernel, cudaFuncAttributeMaxDynamicSharedMemorySize, SMEM);
    cudaFuncSetAttribute(pass2_kernel, cudaFuncAttributeMaxDynamicSharedMemorySize, SMEM);
    cudaFuncSetAttribute(pass3_kernel, cudaFuncAttributeMaxDynamicSharedMemorySize, SMEM);

    dim3 grid(BATCH * 8);   // 256 CTAs, 2 per SM resident

    pass1_kernel<<<grid, THREADS, SMEM>>>(thetas, st_re, st_im);

    cudaLaunchAttribute attrs[1];
    attrs[0].id = cudaLaunchAttributeProgrammaticStreamSerialization;
    attrs[0].val.programmaticStreamSerializationAllowed = 1;

    cudaLaunchConfig_t cfg = {};
    cfg.gridDim = grid;
    cfg.blockDim = dim3(THREADS);
    cfg.dynamicSmemBytes = SMEM;
    cfg.stream = 0;
    cfg.attrs = attrs;
    cfg.numAttrs = 1;

    cudaLaunchKernelEx(&cfg, pass2_kernel, thetas);
    cudaLaunchKernelEx(&cfg, pass3_kernel, thetas, probs);
}